// round 16
// baseline (speedup 1.0000x reference)
#include <cuda_runtime.h>
#include <math.h>

// ---------------------------------------------------------------------------
// Problem constants
// ---------------------------------------------------------------------------
#define NN     1024
#define FF     128
#define MM     256
#define EE     8
#define W1COLS 260           // 2F+4
#define P_TOT  523776        // N*(N-1)/2
#define TILE   32            // i/j tile per block
#define NTILE  32            // N / TILE
#define WEXTRA 32            // extra floats after W2f: b2f[8], w3[8], b3
#define WTOT   (EE * MM + WEXTRA)

typedef unsigned long long ull;

// ---------------------------------------------------------------------------
// Device scratch (no allocations allowed)
// ---------------------------------------------------------------------------
__device__ __align__(16) float g_pa[NN * MM];          // x @ W1a^T
__device__ __align__(16) float g_pb[NN * MM];          // x @ W1b^T
__device__ __align__(16) float g_W2fx[WTOT];           // folded W2 + b2f/w3/b3
__device__ __align__(16) float g_cterm[MM];
__device__ double g_std[NN];
__device__ int    g_stressed[NN];

// Constant copy of folded weights (filled by async D2D memcpy each call).
__constant__ __align__(16) float c_W2f[WTOT];

// ---------------------------------------------------------------------------
// f32x2 packed helpers (FFMA2 path — only reachable via PTX)
// ---------------------------------------------------------------------------
__device__ __forceinline__ ull add2(ull a, ull b) {
    ull r;
    asm("add.rn.f32x2 %0, %1, %2;" : "=l"(r) : "l"(a), "l"(b));
    return r;
}
__device__ __forceinline__ ull fma2(ull a, ull b, ull c) {
    ull r;
    asm("fma.rn.f32x2 %0, %1, %2, %3;" : "=l"(r) : "l"(a), "l"(b), "l"(c));
    return r;
}
__device__ __forceinline__ ull relu2(ull v) {
    float lo = __uint_as_float((unsigned)v);
    float hi = __uint_as_float((unsigned)(v >> 32));
    lo = fmaxf(lo, 0.0f);
    hi = fmaxf(hi, 0.0f);
    return (ull)__float_as_uint(lo) | ((ull)__float_as_uint(hi) << 32);
}

struct __align__(16) F4 { ull lo, hi; };
union U64 { ull u; float2 f; };

// ---------------------------------------------------------------------------
// Stress std: one warp per node, fp64 (a flipped flag is disastrous)
// ---------------------------------------------------------------------------
__global__ void stress_std_kernel(const float* __restrict__ x) {
    int node = blockIdx.x * 4 + (threadIdx.x >> 5);
    int l = threadIdx.x & 31;
    float4 v = *(const float4*)&x[node * FF + l * 4];
    double s  = (double)v.x + (double)v.y + (double)v.z + (double)v.w;
    double s2 = (double)v.x * v.x + (double)v.y * v.y +
                (double)v.z * v.z + (double)v.w * v.w;
    #pragma unroll
    for (int o = 16; o; o >>= 1) {
        s  += __shfl_down_sync(0xffffffffu, s,  o);
        s2 += __shfl_down_sync(0xffffffffu, s2, o);
    }
    if (l == 0) {
        double var = (s2 - s * s / (double)FF) / (double)(FF - 1);
        g_std[node] = sqrt(var > 0.0 ? var : 0.0);
    }
}

// ---------------------------------------------------------------------------
// Prep: stress flags, cterm, BN-fold into W2f/b2f, stash W3/b3
// ---------------------------------------------------------------------------
__global__ void prep_kernel(const float* __restrict__ ctx,
                            const float* __restrict__ W1,
                            const float* __restrict__ b1,
                            const float* __restrict__ gamma,
                            const float* __restrict__ beta,
                            const float* __restrict__ rmean,
                            const float* __restrict__ rvar,
                            const float* __restrict__ W2,
                            const float* __restrict__ b2,
                            const float* __restrict__ W3,
                            const float* __restrict__ b3) {
    int m = threadIdx.x;          // 256 threads
    __shared__ float sbias[MM];
    __shared__ double sred[8];
    __shared__ double smean;

    // ---- stress mean + flags (nodes 4m..4m+3 per thread) ----
    double v0 = g_std[4 * m + 0], v1 = g_std[4 * m + 1];
    double v2 = g_std[4 * m + 2], v3 = g_std[4 * m + 3];
    double s = v0 + v1 + v2 + v3;
    #pragma unroll
    for (int o = 16; o; o >>= 1) s += __shfl_down_sync(0xffffffffu, s, o);
    if ((m & 31) == 0) sred[m >> 5] = s;
    __syncthreads();
    if (m == 0) {
        double u = 0.0;
        #pragma unroll
        for (int w = 0; w < 8; w++) u += sred[w];
        smean = u / (double)NN;
    }
    __syncthreads();
    double mean = smean;
    g_stressed[4 * m + 0] = (v0 > mean) ? 1 : 0;
    g_stressed[4 * m + 1] = (v1 > mean) ? 1 : 0;
    g_stressed[4 * m + 2] = (v2 > mean) ? 1 : 0;
    g_stressed[4 * m + 3] = (v3 > mean) ? 1 : 0;

    // ---- cterm ----
    float ct = b1[m];
    #pragma unroll
    for (int k = 0; k < 4; k++) ct += ctx[k] * W1[m * W1COLS + 2 * FF + k];
    g_cterm[m] = ct;

    // ---- BN fold ----
    float sc = (float)((double)gamma[m] / sqrt((double)rvar[m] + 1e-5));
    float bias = beta[m] - rmean[m] * sc;
    sbias[m] = bias;
    #pragma unroll
    for (int e = 0; e < EE; e++) g_W2fx[e * MM + m] = W2[e * MM + m] * sc;
    __syncthreads();

    int w = m >> 5, l = m & 31;
    if (w < EE) {
        float p = 0.0f;
        for (int mm = l; mm < MM; mm += 32) p += sbias[mm] * W2[w * MM + mm];
        #pragma unroll
        for (int o = 16; o; o >>= 1) p += __shfl_down_sync(0xffffffffu, p, o);
        if (l == 0) g_W2fx[EE * MM + w] = b2[w] + p;
    }
    if (m < EE) g_W2fx[EE * MM + 8 + m] = W3[m];
    if (m == 0) g_W2fx[EE * MM + 16] = b3[0];
    if (m >= 17 && m < WEXTRA) g_W2fx[EE * MM + m] = 0.0f;  // deterministic tail
}

// ---------------------------------------------------------------------------
// GEMM: pa[i,c] = x[i,:]@W1[c,0:128]; pb[i,c] = x[i,:]@W1[c,128:256]
// Tile 64i x 32c, grid (16,16)=256 blocks, 48KB smem -> 4 blocks/SM.
// ---------------------------------------------------------------------------
__global__ __launch_bounds__(256) void gemm_kernel(const float* __restrict__ x,
                                                   const float* __restrict__ W1) {
    __shared__ float xs[64 * FF];   // 32 KB, swizzled (16B-block XOR with row&7)
    __shared__ float ws[32 * FF];   // 16 KB, linear, read broadcast

    int tid = threadIdx.x;
    int i0 = blockIdx.x * 64;
    int c0 = blockIdx.y * 32;       // c in [0,512): <256 -> pa, else pb

    for (int u = tid; u < 64 * 32; u += 256) {
        int r = u >> 5, q = u & 31;
        *(float4*)&xs[r * FF + ((q ^ (r & 7)) << 2)] =
            *(const float4*)&x[(i0 + r) * FF + q * 4];
    }
    for (int u = tid; u < 32 * 32; u += 256) {
        int r = u >> 5, q = u & 31;
        const float* src = (c0 < MM) ? &W1[(c0 + r) * W1COLS + q * 4]
                                     : &W1[(c0 + r - MM) * W1COLS + FF + q * 4];
        *(float4*)&ws[r * FF + q * 4] = *(const float4*)src;
    }
    __syncthreads();

    int l = tid & 31, w = tid >> 5;           // lane -> i, warp -> 4 c cols
    const char* ax = (const char*)&xs[l * FF];  // rows l, l+32
    unsigned xsw = (unsigned)(l & 7) << 4;
    const float* bp = &ws[(4 * w) * FF];

    ull acc[2][4];
    #pragma unroll
    for (int r = 0; r < 2; r++)
        #pragma unroll
        for (int c = 0; c < 4; c++) acc[r][c] = 0ull;

    #pragma unroll 8
    for (int k = 0; k < FF; k += 4) {
        unsigned ko = (unsigned)(k << 2) ^ xsw;
        F4 a0 = *(const F4*)(ax + ko);
        F4 a1 = *(const F4*)(ax + 32 * FF * 4 + ko);
        F4 b0 = *(const F4*)(bp + k);
        F4 b1 = *(const F4*)(bp + FF + k);
        F4 b2v = *(const F4*)(bp + 2 * FF + k);
        F4 b3v = *(const F4*)(bp + 3 * FF + k);
        acc[0][0] = fma2(a0.lo, b0.lo, acc[0][0]);  acc[0][0] = fma2(a0.hi, b0.hi, acc[0][0]);
        acc[0][1] = fma2(a0.lo, b1.lo, acc[0][1]);  acc[0][1] = fma2(a0.hi, b1.hi, acc[0][1]);
        acc[0][2] = fma2(a0.lo, b2v.lo, acc[0][2]); acc[0][2] = fma2(a0.hi, b2v.hi, acc[0][2]);
        acc[0][3] = fma2(a0.lo, b3v.lo, acc[0][3]); acc[0][3] = fma2(a0.hi, b3v.hi, acc[0][3]);
        acc[1][0] = fma2(a1.lo, b0.lo, acc[1][0]);  acc[1][0] = fma2(a1.hi, b0.hi, acc[1][0]);
        acc[1][1] = fma2(a1.lo, b1.lo, acc[1][1]);  acc[1][1] = fma2(a1.hi, b1.hi, acc[1][1]);
        acc[1][2] = fma2(a1.lo, b2v.lo, acc[1][2]); acc[1][2] = fma2(a1.hi, b2v.hi, acc[1][2]);
        acc[1][3] = fma2(a1.lo, b3v.lo, acc[1][3]); acc[1][3] = fma2(a1.hi, b3v.hi, acc[1][3]);
    }

    #pragma unroll
    for (int ii = 0; ii < 2; ii++) {
        int i = i0 + l + 32 * ii;
        float4 v;
        U64 u0; u0.u = acc[ii][0]; v.x = u0.f.x + u0.f.y;
        U64 u1; u1.u = acc[ii][1]; v.y = u1.f.x + u1.f.y;
        U64 u2; u2.u = acc[ii][2]; v.z = u2.f.x + u2.f.y;
        U64 u3; u3.u = acc[ii][3]; v.w = u3.f.x + u3.f.y;
        if (c0 < MM) *(float4*)&g_pa[i * MM + c0 + 4 * w] = v;
        else         *(float4*)&g_pb[i * MM + (c0 - MM) + 4 * w] = v;
    }
}

// ---------------------------------------------------------------------------
// Pair kernel — R10/R14 base, m-loop MANUALLY 2x UNROLLED with double
// buffering: the buffer swap becomes register renaming instead of 8 MOV.64s
// (16 ALU issue slots) per round. Weights are plain per-e LDC (best measured).
// ---------------------------------------------------------------------------
#define SMEM_PAIR (2 * TILE * MM * 4)   // 64 KB

// one 4-m round: relu(add) for 4 pair-combos, then 8 e-steps of 8 fma2
#define PAIR_ROUND(A0, A1, B0, B1, MIDX) do {                                 \
    ull rl0 = relu2(add2((A0).lo, (B0).lo));                                  \
    ull rl1 = relu2(add2((A0).lo, (B1).lo));                                  \
    ull rl2 = relu2(add2((A1).lo, (B0).lo));                                  \
    ull rl3 = relu2(add2((A1).lo, (B1).lo));                                  \
    ull rh0 = relu2(add2((A0).hi, (B0).hi));                                  \
    ull rh1 = relu2(add2((A0).hi, (B1).hi));                                  \
    ull rh2 = relu2(add2((A1).hi, (B0).hi));                                  \
    ull rh3 = relu2(add2((A1).hi, (B1).hi));                                  \
    _Pragma("unroll")                                                         \
    for (int e = 0; e < EE; e++) {                                            \
        F4 w = *(const F4*)&c_W2f[e * MM + (MIDX)];                           \
        acc[0][e] = fma2(rl0, w.lo, acc[0][e]);                               \
        acc[1][e] = fma2(rl1, w.lo, acc[1][e]);                               \
        acc[2][e] = fma2(rl2, w.lo, acc[2][e]);                               \
        acc[3][e] = fma2(rl3, w.lo, acc[3][e]);                               \
        acc[0][e] = fma2(rh0, w.hi, acc[0][e]);                               \
        acc[1][e] = fma2(rh1, w.hi, acc[1][e]);                               \
        acc[2][e] = fma2(rh2, w.hi, acc[2][e]);                               \
        acc[3][e] = fma2(rh3, w.hi, acc[3][e]);                               \
    }                                                                         \
} while (0)

#define PAIR_LOAD(D0, D1, D2, D3, MOFF) do {                                  \
    (D0) = *(const F4*)(pa0 + ((MOFF) ^ xa0));                                \
    (D1) = *(const F4*)(pa1 + ((MOFF) ^ xa1));                                \
    (D2) = *(const F4*)(pb0 + ((MOFF) ^ xb0));                                \
    (D3) = *(const F4*)(pb1 + ((MOFF) ^ xb1));                                \
} while (0)

__global__ __launch_bounds__(256, 2) void pair_kernel(float* __restrict__ out,
                                                      int has_mask) {
    extern __shared__ float sm[];
    float* sa = sm;                       // 32 x 256, swizzled (pa + cterm)
    float* sb = sm + TILE * MM;           // 32 x 256, swizzled (pb)

    // decode (bi, bj), bi <= bj
    int t = blockIdx.x, bi = 0;
    while (t >= NTILE - bi) { t -= NTILE - bi; bi++; }
    int bj = bi + t;
    int i0 = bi * TILE, j0 = bj * TILE;
    int tid = threadIdx.x;

    // cooperative loads, swizzle on 16B blocks: block q -> q ^ (row & 7)
    for (int u = tid; u < TILE * (MM / 4); u += 256) {
        int r = u >> 6, q = u & 63;
        int dst = r * MM + ((q ^ (r & 7)) << 2);
        float4 va = *(const float4*)&g_pa[(i0 + r) * MM + q * 4];
        float4 ct = *(const float4*)&g_cterm[q * 4];
        va.x += ct.x; va.y += ct.y; va.z += ct.z; va.w += ct.w;
        *(float4*)(sa + dst) = va;
        *(float4*)(sb + dst) = *(const float4*)&g_pb[(j0 + r) * MM + q * 4];
    }
    __syncthreads();

    int ti2 = tid >> 4, tj2 = tid & 15;
    int rA = ti2, rB = ti2 + 16;          // i rows
    int sA = tj2, sB = tj2 + 16;          // j rows
    const char* pa0 = (const char*)(sa + rA * MM);
    const char* pa1 = (const char*)(sa + rB * MM);
    const char* pb0 = (const char*)(sb + sA * MM);
    const char* pb1 = (const char*)(sb + sB * MM);
    unsigned xa0 = (unsigned)(rA & 7) << 4;
    unsigned xa1 = (unsigned)(rB & 7) << 4;
    unsigned xb0 = (unsigned)(sA & 7) << 4;
    unsigned xb1 = (unsigned)(sB & 7) << 4;

    ull acc[4][EE];
    #pragma unroll
    for (int p = 0; p < 4; p++)
        #pragma unroll
        for (int e = 0; e < EE; e++) acc[p][e] = 0ull;

    // two operand buffer sets; swap by renaming via 2x manual unroll
    F4 a0, a1, b0, b1;      // buffer A
    F4 c0_, c1_, d0_, d1_;  // buffer B
    PAIR_LOAD(a0, a1, b0, b1, 0u);

    #pragma unroll 1
    for (int m = 0; m < MM; m += 8) {
        unsigned m4 = (unsigned)((m + 4) << 2);
        PAIR_LOAD(c0_, c1_, d0_, d1_, m4);          // prefetch round m+4
        PAIR_ROUND(a0, a1, b0, b1, m);              // compute round m

        unsigned m8 = (unsigned)(((m + 8) & (MM - 1)) << 2);  // wraps: re-read
        PAIR_LOAD(a0, a1, b0, b1, m8);              // prefetch round m+8
        PAIR_ROUND(c0_, c1_, d0_, d1_, m + 4);      // compute round m+4
    }

    // epilogue (constants from constant memory)
    float vb2[EE], vw3[EE];
    #pragma unroll
    for (int e = 0; e < EE; e++) {
        vb2[e] = c_W2f[EE * MM + e];
        vw3[e] = c_W2f[EE * MM + 8 + e];
    }
    float bb3 = c_W2f[EE * MM + 16];

    int li[4] = { rA, rA, rB, rB };
    int lj[4] = { sA, sB, sA, sB };
    #pragma unroll
    for (int p = 0; p < 4; p++) {
        int i = i0 + li[p], j = j0 + lj[p];
        if (j <= i) continue;
        float z = bb3;
        #pragma unroll
        for (int e = 0; e < EE; e++) {
            U64 u; u.u = acc[p][e];
            float h = u.f.x + u.f.y + vb2[e];
            h = fmaxf(h, 0.0f);
            z = fmaf(h, vw3[e], z);
        }
        float s = 1.0f / (1.0f + expf(-z));
        unsigned pidx = (unsigned)(i * (2 * NN - i - 1) / 2 + (j - i - 1));
        out[pidx] = s;
        if (has_mask) {
            bool msk = (s > 0.5f) && g_stressed[i] && g_stressed[j];
            out[P_TOT + pidx] = msk ? 1.0f : 0.0f;
        }
    }
}

// ---------------------------------------------------------------------------
// Launch: side stream runs stress + prep + weight memcpy, overlapping the
// main-stream gemm. pair waits on both (event fork/join, graph-capturable).
// ---------------------------------------------------------------------------
extern "C" void kernel_launch(void* const* d_in, const int* in_sizes, int n_in,
                              void* d_out, int out_size) {
    const float* x     = (const float*)d_in[0];
    const float* ctx   = (const float*)d_in[1];
    const float* W1    = (const float*)d_in[2];
    const float* b1    = (const float*)d_in[3];
    const float* gamma = (const float*)d_in[4];
    const float* beta  = (const float*)d_in[5];
    const float* rmean = (const float*)d_in[6];
    const float* rvar  = (const float*)d_in[7];
    const float* W2    = (const float*)d_in[8];
    const float* b2    = (const float*)d_in[9];
    const float* W3    = (const float*)d_in[10];
    const float* b3    = (const float*)d_in[11];
    float* out = (float*)d_out;

    (void)in_sizes; (void)n_in;

    static cudaStream_t s1 = 0;
    static cudaEvent_t e0 = 0, e1 = 0;
    static void* w2f_dev = 0;
    if (!s1) {
        cudaStreamCreateWithFlags(&s1, cudaStreamNonBlocking);
        cudaEventCreateWithFlags(&e0, cudaEventDisableTiming);
        cudaEventCreateWithFlags(&e1, cudaEventDisableTiming);
        cudaFuncSetAttribute(pair_kernel,
                             cudaFuncAttributeMaxDynamicSharedMemorySize, SMEM_PAIR);
        cudaGetSymbolAddress(&w2f_dev, g_W2fx);
    }

    // fork: side stream does stress + prep + weight copy while main does gemm
    cudaEventRecord(e0, 0);
    cudaStreamWaitEvent(s1, e0, 0);
    stress_std_kernel<<<NN / 4, 128, 0, s1>>>(x);
    prep_kernel<<<1, MM, 0, s1>>>(ctx, W1, b1, gamma, beta, rmean, rvar,
                                  W2, b2, W3, b3);
    cudaMemcpyToSymbolAsync(c_W2f, w2f_dev, WTOT * sizeof(float),
                            0, cudaMemcpyDeviceToDevice, s1);
    cudaEventRecord(e1, s1);

    gemm_kernel<<<dim3(NN / 64, 512 / 32), 256>>>(x, W1);

    // join
    cudaStreamWaitEvent(0, e1, 0);

    int has_mask = (out_size >= 2 * P_TOT) ? 1 : 0;
    int nblocks = NTILE * (NTILE + 1) / 2;   // 528
    pair_kernel<<<nblocks, 256, SMEM_PAIR>>>(out, has_mask);
}

// round 17
// speedup vs baseline: 2.8028x; 2.8028x over previous
#include <cuda_runtime.h>
#include <math.h>

// ---------------------------------------------------------------------------
// Problem constants
// ---------------------------------------------------------------------------
#define NN     1024
#define FF     128
#define MM     256
#define EE     8
#define W1COLS 260           // 2F+4
#define P_TOT  523776        // N*(N-1)/2
#define TILE   32            // i/j tile per block
#define NTILE  32            // N / TILE
#define WEXTRA 32            // extra floats after W2f: b2f[8], w3[8], b3
#define WTOT   (EE * MM + WEXTRA)

typedef unsigned long long ull;

// ---------------------------------------------------------------------------
// Device scratch (no allocations allowed)
// ---------------------------------------------------------------------------
__device__ __align__(16) float g_pa[NN * MM];          // x @ W1a^T
__device__ __align__(16) float g_pb[NN * MM];          // x @ W1b^T
__device__ __align__(16) float g_W2fx[WTOT];           // folded W2 + b2f/w3/b3
__device__ __align__(16) float g_cterm[MM];
__device__ double g_std[NN];
__device__ int    g_stressed[NN];

// Constant copy of folded weights (filled by async D2D memcpy each call).
__constant__ __align__(16) float c_W2f[WTOT];

// ---------------------------------------------------------------------------
// f32x2 packed helpers (FFMA2 path — only reachable via PTX)
// ---------------------------------------------------------------------------
__device__ __forceinline__ ull add2(ull a, ull b) {
    ull r;
    asm("add.rn.f32x2 %0, %1, %2;" : "=l"(r) : "l"(a), "l"(b));
    return r;
}
__device__ __forceinline__ ull fma2(ull a, ull b, ull c) {
    ull r;
    asm("fma.rn.f32x2 %0, %1, %2, %3;" : "=l"(r) : "l"(a), "l"(b), "l"(c));
    return r;
}
// relu on a packed f32x2: mov.b64 {lo,hi} unpack/repack is resolved by
// register-pair allocation (ZERO instructions), unlike C shift/OR which
// emitted real SHF/LOP pack-unpack ops (~32 extra ALU issues per round).
__device__ __forceinline__ ull relu2(ull v) {
    ull r;
    asm("{\n\t"
        ".reg .f32 lo, hi;\n\t"
        "mov.b64 {lo, hi}, %1;\n\t"
        "max.f32 lo, lo, 0f00000000;\n\t"
        "max.f32 hi, hi, 0f00000000;\n\t"
        "mov.b64 %0, {lo, hi};\n\t"
        "}" : "=l"(r) : "l"(v));
    return r;
}

struct __align__(16) F4 { ull lo, hi; };
union U64 { ull u; float2 f; };

// ---------------------------------------------------------------------------
// Stress std: one warp per node, fp64 (a flipped flag is disastrous)
// ---------------------------------------------------------------------------
__global__ void stress_std_kernel(const float* __restrict__ x) {
    int node = blockIdx.x * 4 + (threadIdx.x >> 5);
    int l = threadIdx.x & 31;
    float4 v = *(const float4*)&x[node * FF + l * 4];
    double s  = (double)v.x + (double)v.y + (double)v.z + (double)v.w;
    double s2 = (double)v.x * v.x + (double)v.y * v.y +
                (double)v.z * v.z + (double)v.w * v.w;
    #pragma unroll
    for (int o = 16; o; o >>= 1) {
        s  += __shfl_down_sync(0xffffffffu, s,  o);
        s2 += __shfl_down_sync(0xffffffffu, s2, o);
    }
    if (l == 0) {
        double var = (s2 - s * s / (double)FF) / (double)(FF - 1);
        g_std[node] = sqrt(var > 0.0 ? var : 0.0);
    }
}

// ---------------------------------------------------------------------------
// Prep: stress flags, cterm, BN-fold into W2f/b2f, stash W3/b3
// ---------------------------------------------------------------------------
__global__ void prep_kernel(const float* __restrict__ ctx,
                            const float* __restrict__ W1,
                            const float* __restrict__ b1,
                            const float* __restrict__ gamma,
                            const float* __restrict__ beta,
                            const float* __restrict__ rmean,
                            const float* __restrict__ rvar,
                            const float* __restrict__ W2,
                            const float* __restrict__ b2,
                            const float* __restrict__ W3,
                            const float* __restrict__ b3) {
    int m = threadIdx.x;          // 256 threads
    __shared__ float sbias[MM];
    __shared__ double sred[8];
    __shared__ double smean;

    // ---- stress mean + flags (nodes 4m..4m+3 per thread) ----
    double v0 = g_std[4 * m + 0], v1 = g_std[4 * m + 1];
    double v2 = g_std[4 * m + 2], v3 = g_std[4 * m + 3];
    double s = v0 + v1 + v2 + v3;
    #pragma unroll
    for (int o = 16; o; o >>= 1) s += __shfl_down_sync(0xffffffffu, s, o);
    if ((m & 31) == 0) sred[m >> 5] = s;
    __syncthreads();
    if (m == 0) {
        double u = 0.0;
        #pragma unroll
        for (int w = 0; w < 8; w++) u += sred[w];
        smean = u / (double)NN;
    }
    __syncthreads();
    double mean = smean;
    g_stressed[4 * m + 0] = (v0 > mean) ? 1 : 0;
    g_stressed[4 * m + 1] = (v1 > mean) ? 1 : 0;
    g_stressed[4 * m + 2] = (v2 > mean) ? 1 : 0;
    g_stressed[4 * m + 3] = (v3 > mean) ? 1 : 0;

    // ---- cterm ----
    float ct = b1[m];
    #pragma unroll
    for (int k = 0; k < 4; k++) ct += ctx[k] * W1[m * W1COLS + 2 * FF + k];
    g_cterm[m] = ct;

    // ---- BN fold ----
    float sc = (float)((double)gamma[m] / sqrt((double)rvar[m] + 1e-5));
    float bias = beta[m] - rmean[m] * sc;
    sbias[m] = bias;
    #pragma unroll
    for (int e = 0; e < EE; e++) g_W2fx[e * MM + m] = W2[e * MM + m] * sc;
    __syncthreads();

    int w = m >> 5, l = m & 31;
    if (w < EE) {
        float p = 0.0f;
        for (int mm = l; mm < MM; mm += 32) p += sbias[mm] * W2[w * MM + mm];
        #pragma unroll
        for (int o = 16; o; o >>= 1) p += __shfl_down_sync(0xffffffffu, p, o);
        if (l == 0) g_W2fx[EE * MM + w] = b2[w] + p;
    }
    if (m < EE) g_W2fx[EE * MM + 8 + m] = W3[m];
    if (m == 0) g_W2fx[EE * MM + 16] = b3[0];
    if (m >= 17 && m < WEXTRA) g_W2fx[EE * MM + m] = 0.0f;  // deterministic tail
}

// ---------------------------------------------------------------------------
// GEMM: pa[i,c] = x[i,:]@W1[c,0:128]; pb[i,c] = x[i,:]@W1[c,128:256]
// Tile 128i x 32c, grid (8,16)=128 blocks (single wave), 256 threads.
// (exact R14 version — best measured total)
// ---------------------------------------------------------------------------
__global__ __launch_bounds__(256) void gemm_kernel(const float* __restrict__ x,
                                                   const float* __restrict__ W1) {
    __shared__ float xs[128 * FF];  // 64 KB, swizzled (16B-block XOR with row&7)
    __shared__ float ws[32 * FF];   // 16 KB, linear, read broadcast

    int tid = threadIdx.x;
    int i0 = blockIdx.x * 128;
    int c0 = blockIdx.y * 32;       // c in [0,512): <256 -> pa, else pb

    for (int u = tid; u < 128 * 32; u += 256) {
        int r = u >> 5, q = u & 31;
        *(float4*)&xs[r * FF + ((q ^ (r & 7)) << 2)] =
            *(const float4*)&x[(i0 + r) * FF + q * 4];
    }
    for (int u = tid; u < 32 * 32; u += 256) {
        int r = u >> 5, q = u & 31;
        const float* src = (c0 < MM) ? &W1[(c0 + r) * W1COLS + q * 4]
                                     : &W1[(c0 + r - MM) * W1COLS + FF + q * 4];
        *(float4*)&ws[r * FF + q * 4] = *(const float4*)src;
    }
    __syncthreads();

    int l = tid & 31, w = tid >> 5;           // lane -> i, warp -> 4 c cols
    const char* ax = (const char*)&xs[l * FF];  // rows l, l+32, l+64, l+96
    unsigned xsw = (unsigned)(l & 7) << 4;      // same swizzle for all 4 rows
    const float* bp = &ws[(4 * w) * FF];

    ull acc[4][4];
    #pragma unroll
    for (int r = 0; r < 4; r++)
        #pragma unroll
        for (int c = 0; c < 4; c++) acc[r][c] = 0ull;

    #pragma unroll 4
    for (int k = 0; k < FF; k += 4) {
        unsigned ko = (unsigned)(k << 2) ^ xsw;
        F4 a0 = *(const F4*)(ax + ko);
        F4 a1 = *(const F4*)(ax + 32 * FF * 4 + ko);
        F4 a2 = *(const F4*)(ax + 64 * FF * 4 + ko);
        F4 a3 = *(const F4*)(ax + 96 * FF * 4 + ko);
        F4 b0 = *(const F4*)(bp + k);
        F4 b1 = *(const F4*)(bp + FF + k);
        F4 b2v = *(const F4*)(bp + 2 * FF + k);
        F4 b3v = *(const F4*)(bp + 3 * FF + k);
        acc[0][0] = fma2(a0.lo, b0.lo, acc[0][0]);  acc[0][0] = fma2(a0.hi, b0.hi, acc[0][0]);
        acc[0][1] = fma2(a0.lo, b1.lo, acc[0][1]);  acc[0][1] = fma2(a0.hi, b1.hi, acc[0][1]);
        acc[0][2] = fma2(a0.lo, b2v.lo, acc[0][2]); acc[0][2] = fma2(a0.hi, b2v.hi, acc[0][2]);
        acc[0][3] = fma2(a0.lo, b3v.lo, acc[0][3]); acc[0][3] = fma2(a0.hi, b3v.hi, acc[0][3]);
        acc[1][0] = fma2(a1.lo, b0.lo, acc[1][0]);  acc[1][0] = fma2(a1.hi, b0.hi, acc[1][0]);
        acc[1][1] = fma2(a1.lo, b1.lo, acc[1][1]);  acc[1][1] = fma2(a1.hi, b1.hi, acc[1][1]);
        acc[1][2] = fma2(a1.lo, b2v.lo, acc[1][2]); acc[1][2] = fma2(a1.hi, b2v.hi, acc[1][2]);
        acc[1][3] = fma2(a1.lo, b3v.lo, acc[1][3]); acc[1][3] = fma2(a1.hi, b3v.hi, acc[1][3]);
        acc[2][0] = fma2(a2.lo, b0.lo, acc[2][0]);  acc[2][0] = fma2(a2.hi, b0.hi, acc[2][0]);
        acc[2][1] = fma2(a2.lo, b1.lo, acc[2][1]);  acc[2][1] = fma2(a2.hi, b1.hi, acc[2][1]);
        acc[2][2] = fma2(a2.lo, b2v.lo, acc[2][2]); acc[2][2] = fma2(a2.hi, b2v.hi, acc[2][2]);
        acc[2][3] = fma2(a2.lo, b3v.lo, acc[2][3]); acc[2][3] = fma2(a2.hi, b3v.hi, acc[2][3]);
        acc[3][0] = fma2(a3.lo, b0.lo, acc[3][0]);  acc[3][0] = fma2(a3.hi, b0.hi, acc[3][0]);
        acc[3][1] = fma2(a3.lo, b1.lo, acc[3][1]);  acc[3][1] = fma2(a3.hi, b1.hi, acc[3][1]);
        acc[3][2] = fma2(a3.lo, b2v.lo, acc[3][2]); acc[3][2] = fma2(a3.hi, b2v.hi, acc[3][2]);
        acc[3][3] = fma2(a3.lo, b3v.lo, acc[3][3]); acc[3][3] = fma2(a3.hi, b3v.hi, acc[3][3]);
    }

    #pragma unroll
    for (int ii = 0; ii < 4; ii++) {
        int i = i0 + l + 32 * ii;
        float4 v;
        U64 u0; u0.u = acc[ii][0]; v.x = u0.f.x + u0.f.y;
        U64 u1; u1.u = acc[ii][1]; v.y = u1.f.x + u1.f.y;
        U64 u2; u2.u = acc[ii][2]; v.z = u2.f.x + u2.f.y;
        U64 u3; u3.u = acc[ii][3]; v.w = u3.f.x + u3.f.y;
        if (c0 < MM) *(float4*)&g_pa[i * MM + c0 + 4 * w] = v;
        else         *(float4*)&g_pb[i * MM + (c0 - MM) + 4 * w] = v;
    }
}

// ---------------------------------------------------------------------------
// Pair kernel — EXACT R10/R14 configuration (best measured: 53.2-53.4us),
// with only relu2 reimplemented via mov.b64 pairing (no pack/unpack ALU ops).
// ---------------------------------------------------------------------------
#define SMEM_PAIR (2 * TILE * MM * 4)   // 64 KB

__global__ __launch_bounds__(256, 2) void pair_kernel(float* __restrict__ out,
                                                      int has_mask) {
    extern __shared__ float sm[];
    float* sa = sm;                       // 32 x 256, swizzled (pa + cterm)
    float* sb = sm + TILE * MM;           // 32 x 256, swizzled (pb)

    // decode (bi, bj), bi <= bj
    int t = blockIdx.x, bi = 0;
    while (t >= NTILE - bi) { t -= NTILE - bi; bi++; }
    int bj = bi + t;
    int i0 = bi * TILE, j0 = bj * TILE;
    int tid = threadIdx.x;

    // cooperative loads, swizzle on 16B blocks: block q -> q ^ (row & 7)
    for (int u = tid; u < TILE * (MM / 4); u += 256) {
        int r = u >> 6, q = u & 63;
        int dst = r * MM + ((q ^ (r & 7)) << 2);
        float4 va = *(const float4*)&g_pa[(i0 + r) * MM + q * 4];
        float4 ct = *(const float4*)&g_cterm[q * 4];
        va.x += ct.x; va.y += ct.y; va.z += ct.z; va.w += ct.w;
        *(float4*)(sa + dst) = va;
        *(float4*)(sb + dst) = *(const float4*)&g_pb[(j0 + r) * MM + q * 4];
    }
    __syncthreads();

    int ti2 = tid >> 4, tj2 = tid & 15;
    int rA = ti2, rB = ti2 + 16;          // i rows
    int sA = tj2, sB = tj2 + 16;          // j rows
    const char* pa0 = (const char*)(sa + rA * MM);
    const char* pa1 = (const char*)(sa + rB * MM);
    const char* pb0 = (const char*)(sb + sA * MM);
    const char* pb1 = (const char*)(sb + sB * MM);
    unsigned xa0 = (unsigned)(rA & 7) << 4;
    unsigned xa1 = (unsigned)(rB & 7) << 4;
    unsigned xb0 = (unsigned)(sA & 7) << 4;
    unsigned xb1 = (unsigned)(sB & 7) << 4;

    ull acc[4][EE];
    #pragma unroll
    for (int p = 0; p < 4; p++)
        #pragma unroll
        for (int e = 0; e < EE; e++) acc[p][e] = 0ull;

    // prologue: load round 0
    F4 a0 = *(const F4*)(pa0 + (0u ^ xa0));
    F4 a1 = *(const F4*)(pa1 + (0u ^ xa1));
    F4 b0 = *(const F4*)(pb0 + (0u ^ xb0));
    F4 b1 = *(const F4*)(pb1 + (0u ^ xb1));

    #pragma unroll 1
    for (int m = 0; m < MM; m += 4) {
        // prefetch next round (wraps to 0 on last iter — harmless re-read)
        unsigned mn = (unsigned)(((m + 4) & (MM - 1)) << 2);
        F4 na0 = *(const F4*)(pa0 + (mn ^ xa0));
        F4 na1 = *(const F4*)(pa1 + (mn ^ xa1));
        F4 nb0 = *(const F4*)(pb0 + (mn ^ xb0));
        F4 nb1 = *(const F4*)(pb1 + (mn ^ xb1));

        ull rl0 = relu2(add2(a0.lo, b0.lo));
        ull rl1 = relu2(add2(a0.lo, b1.lo));
        ull rl2 = relu2(add2(a1.lo, b0.lo));
        ull rl3 = relu2(add2(a1.lo, b1.lo));
        ull rh0 = relu2(add2(a0.hi, b0.hi));
        ull rh1 = relu2(add2(a0.hi, b1.hi));
        ull rh2 = relu2(add2(a1.hi, b0.hi));
        ull rh3 = relu2(add2(a1.hi, b1.hi));

        #pragma unroll
        for (int e = 0; e < EE; e++) {
            F4 w = *(const F4*)&c_W2f[e * MM + m];   // uniform -> constant port
            acc[0][e] = fma2(rl0, w.lo, acc[0][e]);
            acc[1][e] = fma2(rl1, w.lo, acc[1][e]);
            acc[2][e] = fma2(rl2, w.lo, acc[2][e]);
            acc[3][e] = fma2(rl3, w.lo, acc[3][e]);
            acc[0][e] = fma2(rh0, w.hi, acc[0][e]);
            acc[1][e] = fma2(rh1, w.hi, acc[1][e]);
            acc[2][e] = fma2(rh2, w.hi, acc[2][e]);
            acc[3][e] = fma2(rh3, w.hi, acc[3][e]);
        }

        a0 = na0; a1 = na1; b0 = nb0; b1 = nb1;
    }

    // epilogue (constants from constant memory)
    float vb2[EE], vw3[EE];
    #pragma unroll
    for (int e = 0; e < EE; e++) {
        vb2[e] = c_W2f[EE * MM + e];
        vw3[e] = c_W2f[EE * MM + 8 + e];
    }
    float bb3 = c_W2f[EE * MM + 16];

    int li[4] = { rA, rA, rB, rB };
    int lj[4] = { sA, sB, sA, sB };
    #pragma unroll
    for (int p = 0; p < 4; p++) {
        int i = i0 + li[p], j = j0 + lj[p];
        if (j <= i) continue;
        float z = bb3;
        #pragma unroll
        for (int e = 0; e < EE; e++) {
            U64 u; u.u = acc[p][e];
            float h = u.f.x + u.f.y + vb2[e];
            h = fmaxf(h, 0.0f);
            z = fmaf(h, vw3[e], z);
        }
        float s = 1.0f / (1.0f + expf(-z));
        unsigned pidx = (unsigned)(i * (2 * NN - i - 1) / 2 + (j - i - 1));
        out[pidx] = s;
        if (has_mask) {
            bool msk = (s > 0.5f) && g_stressed[i] && g_stressed[j];
            out[P_TOT + pidx] = msk ? 1.0f : 0.0f;
        }
    }
}

// ---------------------------------------------------------------------------
// Launch: side stream runs stress + prep + weight memcpy, overlapping the
// main-stream gemm. pair waits on both (event fork/join, graph-capturable).
// ---------------------------------------------------------------------------
extern "C" void kernel_launch(void* const* d_in, const int* in_sizes, int n_in,
                              void* d_out, int out_size) {
    const float* x     = (const float*)d_in[0];
    const float* ctx   = (const float*)d_in[1];
    const float* W1    = (const float*)d_in[2];
    const float* b1    = (const float*)d_in[3];
    const float* gamma = (const float*)d_in[4];
    const float* beta  = (const float*)d_in[5];
    const float* rmean = (const float*)d_in[6];
    const float* rvar  = (const float*)d_in[7];
    const float* W2    = (const float*)d_in[8];
    const float* b2    = (const float*)d_in[9];
    const float* W3    = (const float*)d_in[10];
    const float* b3    = (const float*)d_in[11];
    float* out = (float*)d_out;

    (void)in_sizes; (void)n_in;

    static cudaStream_t s1 = 0;
    static cudaEvent_t e0 = 0, e1 = 0;
    static void* w2f_dev = 0;
    if (!s1) {
        cudaStreamCreateWithFlags(&s1, cudaStreamNonBlocking);
        cudaEventCreateWithFlags(&e0, cudaEventDisableTiming);
        cudaEventCreateWithFlags(&e1, cudaEventDisableTiming);
        cudaFuncSetAttribute(pair_kernel,
                             cudaFuncAttributeMaxDynamicSharedMemorySize, SMEM_PAIR);
        cudaGetSymbolAddress(&w2f_dev, g_W2fx);
    }

    // fork: side stream does stress + prep + weight copy while main does gemm
    cudaEventRecord(e0, 0);
    cudaStreamWaitEvent(s1, e0, 0);
    stress_std_kernel<<<NN / 4, 128, 0, s1>>>(x);
    prep_kernel<<<1, MM, 0, s1>>>(ctx, W1, b1, gamma, beta, rmean, rvar,
                                  W2, b2, W3, b3);
    cudaMemcpyToSymbolAsync(c_W2f, w2f_dev, WTOT * sizeof(float),
                            0, cudaMemcpyDeviceToDevice, s1);
    cudaEventRecord(e1, s1);

    gemm_kernel<<<dim3(NN / 128, 512 / 32), 256>>>(x, W1);

    // join
    cudaStreamWaitEvent(0, e1, 0);

    int has_mask = (out_size >= 2 * P_TOT) ? 1 : 0;
    int nblocks = NTILE * (NTILE + 1) / 2;   // 528
    pair_kernel<<<nblocks, 256, SMEM_PAIR>>>(out, has_mask);
}